// round 2
// baseline (speedup 1.0000x reference)
#include <cuda_runtime.h>
#include <math.h>

// Problem dims (fixed by the dataset)
#define B_ 64
#define S_ 1024
#define D_ 512
#define F_ 256
#define H_ 512

// Scratch (allocation-free rule: __device__ globals)
__device__ float g_stf[B_ * H_];     // tanh(x @ W_sf + b_sf)
__device__ float g_stx[B_ * H_];     // tanh(x @ W_se + b_se)
__device__ float g_se[S_ * B_];      // score_enc_outs [S,B]
__device__ float g_sf[S_ * B_];      // score_fields   [S,B]
__device__ float g_ctx[B_ * D_];     // context [B,D]

// ---------------------------------------------------------------------------
// K1: state vectors. grid=B_, block=512 (one thread per h)
// ---------------------------------------------------------------------------
__global__ void state_kernel(const float* __restrict__ x,
                             const float* __restrict__ Wsf, const float* __restrict__ bsf,
                             const float* __restrict__ Wse, const float* __restrict__ bse)
{
    __shared__ float xs[D_];
    int b = blockIdx.x, h = threadIdx.x;
    xs[h] = x[b * D_ + h];
    __syncthreads();
    float a0 = bsf[h], a1 = bse[h];
#pragma unroll 8
    for (int k = 0; k < D_; k++) {
        float xv = xs[k];
        a0 += xv * Wsf[k * H_ + h];
        a1 += xv * Wse[k * H_ + h];
    }
    g_stf[b * H_ + h] = tanhf(a0);
    g_stx[b * H_ + h] = tanhf(a1);
}

// ---------------------------------------------------------------------------
// K2: fused score GEMM.  score[s,b] = sum_h tanh(A[b,s,:]@W[:,h] + bias[h]) * state[b,h]
// Tiling: BLOCK_M=64 (s rows), BLOCK_N=128 (h), BK=32. 256 threads, 4x8 micro-tile.
// PHASE 0: enc path (state=g_stx, out=g_se).  PHASE 1: fields (state=g_stf, out=g_sf).
// ---------------------------------------------------------------------------
template<int K, int PHASE>
__global__ __launch_bounds__(256, 2) void score_kernel(
    const float* __restrict__ A,     // [B_, S_, K]
    const float* __restrict__ W,     // [K, H_]
    const float* __restrict__ bias)  // [H_]
{
    __shared__ float As[32][68];     // [k][m], padded (stride 68: float4-aligned)
    __shared__ float Bs[32][128];    // [k][n]

    const int b  = blockIdx.y;
    const int s0 = blockIdx.x * 64;
    const int tid = threadIdx.x;
    const int tx = tid & 15;         // column group (16)
    const int ty = tid >> 4;         // row group (16), rows = ty*4 .. ty*4+3

    const float* __restrict__ Ab = A + ((size_t)b * S_ + s0) * K;
    const float* __restrict__ st = (PHASE == 0 ? g_stx : g_stf) + b * H_;
    float* __restrict__ score = (PHASE == 0 ? g_se : g_sf);

    float scoreAcc[4] = {0.f, 0.f, 0.f, 0.f};

    for (int n0 = 0; n0 < H_; n0 += 128) {
        float acc[4][8];
#pragma unroll
        for (int i = 0; i < 4; i++)
#pragma unroll
            for (int j = 0; j < 8; j++) acc[i][j] = 0.f;

        for (int k0 = 0; k0 < K; k0 += 32) {
            // Load A tile (64 rows x 32 k), transpose into As[k][m]
#pragma unroll
            for (int p = 0; p < 2; p++) {
                int idx = p * 256 + tid;
                int row = idx >> 3;              // 0..63
                int kq  = (idx & 7) * 4;         // 0,4,..,28
                float4 v = *(const float4*)(Ab + (size_t)row * K + k0 + kq);
                As[kq + 0][row] = v.x;
                As[kq + 1][row] = v.y;
                As[kq + 2][row] = v.z;
                As[kq + 3][row] = v.w;
            }
            // Load B tile (32 k x 128 n)
#pragma unroll
            for (int p = 0; p < 4; p++) {
                int lin = p * 256 + tid;         // float4 index, 1024 total
                int r = lin >> 5;                // 0..31
                int c = (lin & 31) * 4;          // 0..124
                *(float4*)&Bs[r][c] = *(const float4*)(W + (size_t)(k0 + r) * H_ + n0 + c);
            }
            __syncthreads();

#pragma unroll
            for (int kk = 0; kk < 32; kk++) {
                float4 a  = *(const float4*)&As[kk][ty * 4];
                float4 b0 = *(const float4*)&Bs[kk][tx * 4];
                float4 b1 = *(const float4*)&Bs[kk][64 + tx * 4];
                float av[4] = {a.x, a.y, a.z, a.w};
                float bv[8] = {b0.x, b0.y, b0.z, b0.w, b1.x, b1.y, b1.z, b1.w};
#pragma unroll
                for (int i = 0; i < 4; i++)
#pragma unroll
                    for (int j = 0; j < 8; j++)
                        acc[i][j] += av[i] * bv[j];
            }
            __syncthreads();
        }

        // Epilogue: tanh + dot with state, accumulate per-row partial score
#pragma unroll
        for (int j = 0; j < 8; j++) {
            int h = n0 + (j < 4 ? tx * 4 + j : 64 + tx * 4 + (j - 4));
            float bv = bias[h];
            float sv = st[h];
#pragma unroll
            for (int i = 0; i < 4; i++)
                scoreAcc[i] += tanhf(acc[i][j] + bv) * sv;
        }
    }

    // Reduce over the 16 tx lanes (tx occupies low 4 bits of the lane id)
#pragma unroll
    for (int off = 1; off < 16; off <<= 1) {
#pragma unroll
        for (int i = 0; i < 4; i++)
            scoreAcc[i] += __shfl_xor_sync(0xffffffffu, scoreAcc[i], off);
    }
    if (tx == 0) {
#pragma unroll
        for (int i = 0; i < 4; i++)
            score[(s0 + ty * 4 + i) * B_ + b] = scoreAcc[i];
    }
}

// ---------------------------------------------------------------------------
// K3: dual softmax over S + gamma. grid=B_, block=256.
// gamma[s] = ee[s]*ef[s] / (P + 1e-6*Ze*Zf)   (exact rewrite of the reference)
// ---------------------------------------------------------------------------
__global__ void gamma_kernel(float* __restrict__ gamma_out /* [S_,B_] */)
{
    __shared__ float red[256];
    __shared__ float tbuf[S_];
    const int b = blockIdx.x, tid = threadIdx.x;

    float se[4], sf[4];
    float mE = -1e30f, mF = -1e30f;
#pragma unroll
    for (int i = 0; i < 4; i++) {
        int s = tid + i * 256;
        se[i] = g_se[s * B_ + b];
        sf[i] = g_sf[s * B_ + b];
        mE = fmaxf(mE, se[i]);
        mF = fmaxf(mF, sf[i]);
    }

    auto blockMax = [&](float v) -> float {
        red[tid] = v; __syncthreads();
        for (int st = 128; st > 0; st >>= 1) {
            if (tid < st) red[tid] = fmaxf(red[tid], red[tid + st]);
            __syncthreads();
        }
        float r = red[0]; __syncthreads(); return r;
    };
    auto blockSum = [&](float v) -> float {
        red[tid] = v; __syncthreads();
        for (int st = 128; st > 0; st >>= 1) {
            if (tid < st) red[tid] += red[tid + st];
            __syncthreads();
        }
        float r = red[0]; __syncthreads(); return r;
    };

    mE = blockMax(mE);
    mF = blockMax(mF);

    float ze = 0.f, zf = 0.f, p = 0.f;
#pragma unroll
    for (int i = 0; i < 4; i++) {
        float ee = expf(se[i] - mE);
        float ef = expf(sf[i] - mF);
        ze += ee; zf += ef;
        float t = ee * ef;
        p += t;
        tbuf[tid + i * 256] = t;
    }
    ze = blockSum(ze);
    zf = blockSum(zf);
    p  = blockSum(p);

    float inv = 1.0f / (p + 1e-6f * ze * zf);
#pragma unroll
    for (int i = 0; i < 4; i++) {
        int s = tid + i * 256;
        gamma_out[s * B_ + b] = tbuf[s] * inv;
    }
}

// ---------------------------------------------------------------------------
// K4: context[b,d] = sum_s gamma[s,b] * enc[b,s,d]. grid=B_, block=512.
// ---------------------------------------------------------------------------
__global__ void context_kernel(const float* __restrict__ enc,
                               const float* __restrict__ gamma /* [S_,B_] */)
{
    __shared__ float gs[S_];
    const int b = blockIdx.x, d = threadIdx.x;
    gs[d]        = gamma[d * B_ + b];
    gs[d + 512]  = gamma[(d + 512) * B_ + b];
    __syncthreads();
    const float* __restrict__ e = enc + (size_t)b * S_ * D_;
    float acc = 0.f;
#pragma unroll 4
    for (int s = 0; s < S_; s++)
        acc += gs[s] * e[(size_t)s * D_ + d];
    g_ctx[b * D_ + d] = acc;
}

// ---------------------------------------------------------------------------
// K5: out[b,h] = tanh([context,x] @ W_g + b_g). grid=B_, block=512.
// ---------------------------------------------------------------------------
__global__ void out_kernel(const float* __restrict__ x,
                           const float* __restrict__ Wg, const float* __restrict__ bg,
                           float* __restrict__ out)
{
    __shared__ float cx[2 * D_];
    const int b = blockIdx.x, h = threadIdx.x;
    cx[h]       = g_ctx[b * D_ + h];
    cx[D_ + h]  = x[b * D_ + h];
    __syncthreads();
    float acc = bg[h];
#pragma unroll 8
    for (int k = 0; k < 2 * D_; k++)
        acc += cx[k] * Wg[(size_t)k * H_ + h];
    out[b * H_ + h] = tanhf(acc);
}

// ---------------------------------------------------------------------------
extern "C" void kernel_launch(void* const* d_in, const int* in_sizes, int n_in,
                              void* d_out, int out_size)
{
    const float* x    = (const float*)d_in[0];
    const float* enc  = (const float*)d_in[1];
    const float* fld  = (const float*)d_in[2];
    const float* Wf   = (const float*)d_in[3];
    const float* bf   = (const float*)d_in[4];
    const float* We   = (const float*)d_in[5];
    const float* be   = (const float*)d_in[6];
    const float* Wsf  = (const float*)d_in[7];
    const float* bsf  = (const float*)d_in[8];
    const float* Wse  = (const float*)d_in[9];
    const float* bse  = (const float*)d_in[10];
    const float* Wg   = (const float*)d_in[11];
    const float* bg   = (const float*)d_in[12];

    float* out    = (float*)d_out;              // [B,H] = 32768 floats
    float* gammas = out + B_ * H_;              // [S,B] = 65536 floats

    state_kernel<<<B_, 512>>>(x, Wsf, bsf, Wse, bse);

    dim3 sgrid(S_ / 64, B_);
    score_kernel<D_, 0><<<sgrid, 256>>>(enc, We, be);   // enc path -> g_se (uses g_stx)
    score_kernel<F_, 1><<<sgrid, 256>>>(fld, Wf, bf);   // fields   -> g_sf (uses g_stf)

    gamma_kernel<<<B_, 256>>>(gammas);
    context_kernel<<<B_, 512>>>(enc, gammas);
    out_kernel<<<B_, 512>>>(x, Wg, bg, out);
}

// round 9
// speedup vs baseline: 1.7207x; 1.7207x over previous
#include <cuda_runtime.h>
#include <cuda_bf16.h>
#include <math.h>
#include <stdint.h>

// Problem dims (fixed by the dataset)
#define B_ 64
#define S_ 1024
#define D_ 512
#define F_ 256
#define H_ 512

// ---------------------------------------------------------------------------
// Scratch (__device__ globals; no allocations allowed)
// ---------------------------------------------------------------------------
__device__ float g_stf[B_ * H_];
__device__ float g_stx[B_ * H_];
__device__ float g_se[S_ * B_];
__device__ float g_sf[S_ * B_];
__device__ float g_ctx[B_ * D_];
// Split-bf16 transposed weights: [H][K]
__device__ __nv_bfloat16 g_Weh[H_ * D_];
__device__ __nv_bfloat16 g_Wel[H_ * D_];
__device__ __nv_bfloat16 g_Wfh[H_ * F_];
__device__ __nv_bfloat16 g_Wfl[H_ * F_];

// ---------------------------------------------------------------------------
// Warp-level bf16 MMA (sm_80+ baseline PTX; works on plain sm_103 target)
// D(f32)[16x8] += A(bf16)[16x16] * B(bf16)[16x8]
// ---------------------------------------------------------------------------
__device__ __forceinline__ void mma_bf16(float* c, const uint32_t* a,
                                         uint32_t b0, uint32_t b1) {
    asm volatile(
        "mma.sync.aligned.m16n8k16.row.col.f32.bf16.bf16.f32 "
        "{%0,%1,%2,%3}, {%4,%5,%6,%7}, {%8,%9}, {%0,%1,%2,%3};\n"
        : "+f"(c[0]), "+f"(c[1]), "+f"(c[2]), "+f"(c[3])
        : "r"(a[0]), "r"(a[1]), "r"(a[2]), "r"(a[3]), "r"(b0), "r"(b1));
}

__device__ __forceinline__ uint32_t pack2bf(float a, float b) {
    __nv_bfloat162 t;
    t.x = __float2bfloat16(a);
    t.y = __float2bfloat16(b);
    return *reinterpret_cast<uint32_t*>(&t);
}

// ---------------------------------------------------------------------------
// W split+transpose: W[K][H] fp32 -> Wt_hi/lo [H][K] bf16
// ---------------------------------------------------------------------------
__global__ void wconv_kernel(const float* __restrict__ W,
                             __nv_bfloat16* __restrict__ Wh,
                             __nv_bfloat16* __restrict__ Wl, int K)
{
    int h = blockIdx.x;
    for (int k = threadIdx.x; k < K; k += blockDim.x) {
        float v = W[(size_t)k * H_ + h];
        __nv_bfloat16 hi = __float2bfloat16(v);
        float lo = v - __bfloat162float(hi);
        Wh[(size_t)h * K + k] = hi;
        Wl[(size_t)h * K + k] = __float2bfloat16(lo);
    }
}

// ---------------------------------------------------------------------------
// K1: state vectors
// ---------------------------------------------------------------------------
__global__ void state_kernel(const float* __restrict__ x,
                             const float* __restrict__ Wsf, const float* __restrict__ bsf,
                             const float* __restrict__ Wse, const float* __restrict__ bse)
{
    __shared__ float xs[D_];
    int b = blockIdx.x, h = threadIdx.x;
    xs[h] = x[b * D_ + h];
    __syncthreads();
    float a0 = bsf[h], a1 = bse[h];
#pragma unroll 8
    for (int k = 0; k < D_; k++) {
        float xv = xs[k];
        a0 += xv * Wsf[k * H_ + h];
        a1 += xv * Wse[k * H_ + h];
    }
    g_stf[b * H_ + h] = tanhf(a0);
    g_stx[b * H_ + h] = tanhf(a1);
}

// ---------------------------------------------------------------------------
// K2: fused score GEMM on tensor cores (mma.sync, split-bf16 3-MMA).
//   score[s,b] = sum_h tanh(A[b,s,:] @ W[:,h] + bias[h]) * state[b,h]
// CTA: 256 threads (8 warps as 4(M) x 2(N)), M=128 s-rows, N-block=128 h,
// BK=32. Warp tile 32x64. acc fp32 in registers (64/thread).
// ---------------------------------------------------------------------------
#define APAD 40   // row stride in bf16 elements (80 B): conflict-free frags

template<int K, int PHASE>
__global__ __launch_bounds__(256, 2) void score_mma(
    const float* __restrict__ A,               // [B_, S_, K] fp32
    const __nv_bfloat16* __restrict__ Wh,      // [H_, K]
    const __nv_bfloat16* __restrict__ Wl,      // [H_, K]
    const float* __restrict__ bias)            // [H_]
{
    __shared__ __align__(16) __nv_bfloat16 Ah_s[128][APAD];
    __shared__ __align__(16) __nv_bfloat16 Al_s[128][APAD];
    __shared__ __align__(16) __nv_bfloat16 Bh_s[128][APAD];
    __shared__ __align__(16) __nv_bfloat16 Bl_s[128][APAD];
    __shared__ float bias_sh[H_];
    __shared__ float st_sh[H_];
    __shared__ float partial_sh[128];

    const int tid  = threadIdx.x;
    const int wid  = tid >> 5;
    const int lane = tid & 31;
    const int warpM = wid & 3;        // rows warpM*32
    const int warpN = wid >> 2;       // cols warpN*64
    const int g = lane >> 2;          // 0..7
    const int t = lane & 3;           // 0..3

    const int b  = blockIdx.y;
    const int s0 = blockIdx.x * 128;

    const float* __restrict__ Ab = A + ((size_t)b * S_ + s0) * K;
    const float* __restrict__ st = (PHASE == 0 ? g_stx : g_stf) + b * H_;

    for (int i = tid; i < H_; i += 256) { bias_sh[i] = bias[i]; st_sh[i] = st[i]; }
    __syncthreads();

    float scoreRow[4] = {0.f, 0.f, 0.f, 0.f};   // [mt*2 + rowhalf]

    for (int n0i = 0; n0i < 4; n0i++) {
        const int h0 = n0i * 128;
        float acc[2][8][4];
#pragma unroll
        for (int mt = 0; mt < 2; mt++)
#pragma unroll
            for (int nt = 0; nt < 8; nt++)
#pragma unroll
                for (int j = 0; j < 4; j++) acc[mt][nt][j] = 0.f;

        for (int k0 = 0; k0 < K; k0 += 32) {
            // ---- A tile: 128 rows x 32 k fp32 -> split bf16 hi/lo ----
#pragma unroll
            for (int p = 0; p < 4; p++) {
                int idx = p * 256 + tid;          // 0..1023
                int r  = idx >> 3;                // 0..127
                int c4 = idx & 7;                 // float4 col
                float4 v = *(const float4*)(Ab + (size_t)r * K + k0 + c4 * 4);
                __nv_bfloat16 h0v = __float2bfloat16(v.x);
                __nv_bfloat16 h1v = __float2bfloat16(v.y);
                __nv_bfloat16 h2v = __float2bfloat16(v.z);
                __nv_bfloat16 h3v = __float2bfloat16(v.w);
                uint2 hv, lv;
                {
                    __nv_bfloat162 t01; t01.x = h0v; t01.y = h1v;
                    __nv_bfloat162 t23; t23.x = h2v; t23.y = h3v;
                    hv.x = *reinterpret_cast<uint32_t*>(&t01);
                    hv.y = *reinterpret_cast<uint32_t*>(&t23);
                }
                lv.x = pack2bf(v.x - __bfloat162float(h0v), v.y - __bfloat162float(h1v));
                lv.y = pack2bf(v.z - __bfloat162float(h2v), v.w - __bfloat162float(h3v));
                *(uint2*)&Ah_s[r][c4 * 4] = hv;
                *(uint2*)&Al_s[r][c4 * 4] = lv;
            }
            // ---- B tile: 128 h-rows x 32 k bf16 (hi/lo) ----
#pragma unroll
            for (int p = 0; p < 2; p++) {
                int idx = p * 256 + tid;          // 0..511
                int r  = idx >> 2;                // 0..127
                int c8 = idx & 3;                 // uint4 col (8 bf16)
                *(uint4*)&Bh_s[r][c8 * 8] =
                    *(const uint4*)(Wh + (size_t)(h0 + r) * K + k0 + c8 * 8);
                *(uint4*)&Bl_s[r][c8 * 8] =
                    *(const uint4*)(Wl + (size_t)(h0 + r) * K + k0 + c8 * 8);
            }
            __syncthreads();

#pragma unroll
            for (int kk = 0; kk < 2; kk++) {      // two k16 halves
                const int kb = kk * 16;
                uint32_t ah[2][4], al[2][4];
#pragma unroll
                for (int mt = 0; mt < 2; mt++) {
                    int r0 = warpM * 32 + mt * 16 + g;
                    ah[mt][0] = *(const uint32_t*)&Ah_s[r0    ][kb + 2 * t];
                    ah[mt][1] = *(const uint32_t*)&Ah_s[r0 + 8][kb + 2 * t];
                    ah[mt][2] = *(const uint32_t*)&Ah_s[r0    ][kb + 2 * t + 8];
                    ah[mt][3] = *(const uint32_t*)&Ah_s[r0 + 8][kb + 2 * t + 8];
                    al[mt][0] = *(const uint32_t*)&Al_s[r0    ][kb + 2 * t];
                    al[mt][1] = *(const uint32_t*)&Al_s[r0 + 8][kb + 2 * t];
                    al[mt][2] = *(const uint32_t*)&Al_s[r0    ][kb + 2 * t + 8];
                    al[mt][3] = *(const uint32_t*)&Al_s[r0 + 8][kb + 2 * t + 8];
                }
#pragma unroll
                for (int nt = 0; nt < 8; nt++) {
                    int col = warpN * 64 + nt * 8 + g;
                    uint32_t bh0 = *(const uint32_t*)&Bh_s[col][kb + 2 * t];
                    uint32_t bh1 = *(const uint32_t*)&Bh_s[col][kb + 2 * t + 8];
                    uint32_t bl0 = *(const uint32_t*)&Bl_s[col][kb + 2 * t];
                    uint32_t bl1 = *(const uint32_t*)&Bl_s[col][kb + 2 * t + 8];
#pragma unroll
                    for (int mt = 0; mt < 2; mt++) {
                        mma_bf16(acc[mt][nt], ah[mt], bh0, bh1);
                        mma_bf16(acc[mt][nt], ah[mt], bl0, bl1);
                        mma_bf16(acc[mt][nt], al[mt], bh0, bh1);
                    }
                }
            }
            __syncthreads();
        }

        // ---- epilogue for this N-block: tanh(+bias) . state ----
#pragma unroll
        for (int mt = 0; mt < 2; mt++)
#pragma unroll
            for (int nt = 0; nt < 8; nt++)
#pragma unroll
                for (int j = 0; j < 4; j++) {
                    int h = h0 + warpN * 64 + nt * 8 + 2 * t + (j & 1);
                    float v = tanhf(acc[mt][nt][j] + bias_sh[h]) * st_sh[h];
                    scoreRow[mt * 2 + (j >> 1)] += v;
                }
    }

    // Reduce across the 4 t-lanes of each quad (same row g)
#pragma unroll
    for (int off = 1; off < 4; off <<= 1)
#pragma unroll
        for (int i = 0; i < 4; i++)
            scoreRow[i] += __shfl_xor_sync(0xffffffffu, scoreRow[i], off);

    // Combine warpN halves via smem, write scores
    if (t == 0 && warpN == 1) {
#pragma unroll
        for (int mt = 0; mt < 2; mt++)
#pragma unroll
            for (int rh = 0; rh < 2; rh++) {
                int r = warpM * 32 + mt * 16 + rh * 8 + g;
                partial_sh[r] = scoreRow[mt * 2 + rh];
            }
    }
    __syncthreads();
    if (t == 0 && warpN == 0) {
        float* scoreOut = (PHASE == 0 ? g_se : g_sf);
#pragma unroll
        for (int mt = 0; mt < 2; mt++)
#pragma unroll
            for (int rh = 0; rh < 2; rh++) {
                int r = warpM * 32 + mt * 16 + rh * 8 + g;
                scoreOut[(size_t)(s0 + r) * B_ + b] =
                    scoreRow[mt * 2 + rh] + partial_sh[r];
            }
    }
}

// ---------------------------------------------------------------------------
// K3: dual softmax + gamma
// ---------------------------------------------------------------------------
__global__ void gamma_kernel(float* __restrict__ gamma_out)
{
    __shared__ float red[256];
    __shared__ float tbuf[S_];
    const int b = blockIdx.x, tid = threadIdx.x;

    float se[4], sf[4];
    float mE = -1e30f, mF = -1e30f;
#pragma unroll
    for (int i = 0; i < 4; i++) {
        int s = tid + i * 256;
        se[i] = g_se[s * B_ + b];
        sf[i] = g_sf[s * B_ + b];
        mE = fmaxf(mE, se[i]);
        mF = fmaxf(mF, sf[i]);
    }
    auto blockMax = [&](float v) -> float {
        red[tid] = v; __syncthreads();
        for (int st = 128; st > 0; st >>= 1) {
            if (tid < st) red[tid] = fmaxf(red[tid], red[tid + st]);
            __syncthreads();
        }
        float r = red[0]; __syncthreads(); return r;
    };
    auto blockSum = [&](float v) -> float {
        red[tid] = v; __syncthreads();
        for (int st = 128; st > 0; st >>= 1) {
            if (tid < st) red[tid] += red[tid + st];
            __syncthreads();
        }
        float r = red[0]; __syncthreads(); return r;
    };
    mE = blockMax(mE);
    mF = blockMax(mF);

    float ze = 0.f, zf = 0.f, p = 0.f;
#pragma unroll
    for (int i = 0; i < 4; i++) {
        float ee = expf(se[i] - mE);
        float ef = expf(sf[i] - mF);
        ze += ee; zf += ef;
        float t = ee * ef;
        p += t;
        tbuf[tid + i * 256] = t;
    }
    ze = blockSum(ze);
    zf = blockSum(zf);
    p  = blockSum(p);

    float inv = 1.0f / (p + 1e-6f * ze * zf);
#pragma unroll
    for (int i = 0; i < 4; i++) {
        int s = tid + i * 256;
        gamma_out[s * B_ + b] = tbuf[s] * inv;
    }
}

// ---------------------------------------------------------------------------
// K4: context
// ---------------------------------------------------------------------------
__global__ void context_kernel(const float* __restrict__ enc,
                               const float* __restrict__ gamma)
{
    __shared__ float gs[S_];
    const int b = blockIdx.x, d = threadIdx.x;
    gs[d]       = gamma[d * B_ + b];
    gs[d + 512] = gamma[(d + 512) * B_ + b];
    __syncthreads();
    const float* __restrict__ e = enc + (size_t)b * S_ * D_;
    float acc = 0.f;
#pragma unroll 4
    for (int s = 0; s < S_; s++)
        acc += gs[s] * e[(size_t)s * D_ + d];
    g_ctx[b * D_ + d] = acc;
}

// ---------------------------------------------------------------------------
// K5: output GEMM + tanh
// ---------------------------------------------------------------------------
__global__ void out_kernel(const float* __restrict__ x,
                           const float* __restrict__ Wg, const float* __restrict__ bg,
                           float* __restrict__ out)
{
    __shared__ float cx[2 * D_];
    const int b = blockIdx.x, h = threadIdx.x;
    cx[h]      = g_ctx[b * D_ + h];
    cx[D_ + h] = x[b * D_ + h];
    __syncthreads();
    float acc = bg[h];
#pragma unroll 8
    for (int k = 0; k < 2 * D_; k++)
        acc += cx[k] * Wg[(size_t)k * H_ + h];
    out[b * H_ + h] = tanhf(acc);
}

// ---------------------------------------------------------------------------
extern "C" void kernel_launch(void* const* d_in, const int* in_sizes, int n_in,
                              void* d_out, int out_size)
{
    const float* x    = (const float*)d_in[0];
    const float* enc  = (const float*)d_in[1];
    const float* fld  = (const float*)d_in[2];
    const float* Wf   = (const float*)d_in[3];
    const float* bf   = (const float*)d_in[4];
    const float* We   = (const float*)d_in[5];
    const float* be   = (const float*)d_in[6];
    const float* Wsf  = (const float*)d_in[7];
    const float* bsf  = (const float*)d_in[8];
    const float* Wse  = (const float*)d_in[9];
    const float* bse  = (const float*)d_in[10];
    const float* Wg   = (const float*)d_in[11];
    const float* bg   = (const float*)d_in[12];

    float* out    = (float*)d_out;
    float* gammas = out + B_ * H_;

    // Resolve device-global addresses (host-side, no allocation)
    __nv_bfloat16 *pWeh, *pWel, *pWfh, *pWfl;
    cudaGetSymbolAddress((void**)&pWeh, g_Weh);
    cudaGetSymbolAddress((void**)&pWel, g_Wel);
    cudaGetSymbolAddress((void**)&pWfh, g_Wfh);
    cudaGetSymbolAddress((void**)&pWfl, g_Wfl);

    wconv_kernel<<<H_, 256>>>(We, pWeh, pWel, D_);
    wconv_kernel<<<H_, 256>>>(Wf, pWfh, pWfl, F_);
    state_kernel<<<B_, 512>>>(x, Wsf, bsf, Wse, bse);

    dim3 sgrid(S_ / 128, B_);
    score_mma<D_, 0><<<sgrid, 256>>>(enc, pWeh, pWel, be);   // enc -> g_se (uses g_stx)
    score_mma<F_, 1><<<sgrid, 256>>>(fld, pWfh, pWfl, bf);   // fields -> g_sf (uses g_stf)

    gamma_kernel<<<B_, 256>>>(gammas);
    context_kernel<<<B_, 512>>>(enc, gammas);
    out_kernel<<<B_, 512>>>(x, Wg, bg, out);
}